// round 16
// baseline (speedup 1.0000x reference)
#include <cuda_runtime.h>
#include <cuda_fp16.h>
#include <math.h>

#define BB 64
#define SS 1024
#define TT 511
#define VV 1024
#define EE 512
#define UU 1024

#define NCTA 592
#define NTH  128

#define BM 64
#define BN 32
#define BK 16
#define ASTR 68
#define SH_FLOATS (2*BK*ASTR + 2*BK*BN)   // 3200 floats = 12.8 KB

// fused-phase job ranges: [lstm1 | attn1 | q | score | ctx | attn2 | out | lstm2]
#define F_A1   384     // lstm1: [0,384)
#define F_Q    448     // attn1: [384,448)
#define F_SC   512     // q:     [448,512)
#define F_CTX  4608    // score: [512,4608)
#define F_A2   5120    // ctx:   [4608,5120)
#define F_OUT  5248    // attn2: [5120,5248)
#define F_L2   5504    // out:   [5248,5504)
#define F_END  5760    // lstm2: [5504,5760)

// ---------------- device scratch ----------------
__device__ __align__(16) __half g_keysh[(size_t)BB * SS * UU];  // 128 MB
__device__ __align__(16) __half g_memh[(size_t)BB * SS * UU];   // 128 MB
__device__ __align__(16) __half g_WkrH[(size_t)2560 * 4096];    // 21 MB
__device__ __align__(16) __half g_WqH[1024 * 1024];
__device__ __align__(16) __half g_WaH[2048 * 1024];
__device__ __align__(16) __half g_WmH[1024 * 1024];
__device__ __align__(16) float g_z[BB * 4 * UU];
__device__ __align__(16) float g_h[BB * UU];
__device__ __align__(16) float g_c[BB * UU];
__device__ __align__(16) float g_attn[BB * UU];
__device__ __align__(16) float g_q[BB * UU];
__device__ __align__(16) float g_score[BB * SS];
__device__ __align__(16) float g_ctx[BB * UU];
__device__ unsigned g_sdone[BB];
__device__ unsigned g_qdone = 0;
__device__ unsigned g_ctxdone = 0;
__device__ unsigned g_attndone = 0;

// ---------------- grid barrier ----------------
__device__ unsigned g_bar_cnt = 0;
__device__ volatile unsigned g_bar_gen = 0;

__device__ __forceinline__ void grid_sync() {
    __syncthreads();
    __threadfence();
    if (threadIdx.x == 0) {
        unsigned gen = g_bar_gen;
        if (atomicAdd(&g_bar_cnt, 1u) == NCTA - 1u) {
            g_bar_cnt = 0;
            __threadfence();
            g_bar_gen = gen + 1u;
        } else {
            while (g_bar_gen == gen) { }
        }
    }
    __syncthreads();
}

// publish: CTA-wide fence then bump counter
__device__ __forceinline__ void publish(unsigned* ctr) {
    __threadfence();
    __syncthreads();
    if (threadIdx.x == 0) atomicAdd(ctr, 1u);
}
// acquire: spin until counter reaches target, then flush L1
__device__ __forceinline__ void wait_ctr(unsigned* ctr, unsigned target) {
    if (threadIdx.x == 0) {
        while (atomicAdd(ctr, 0u) < target) { }
    }
    __syncthreads();
    __threadfence();
}

// ---------------- math helpers ----------------
__device__ __forceinline__ float sigmoid_acc(float x) {
    return 1.0f / (1.0f + expf(-x));
}
__device__ __forceinline__ void lstm_one(float zi, float zf, float zg, float zo,
                                         float c, float& cn, float& hn) {
    float i0 = sigmoid_acc(zi);
    float f0 = sigmoid_acc(zf);
    float g0 = tanhf(zg);
    float o0 = sigmoid_acc(zo);
    cn = f0 * c + i0 * g0;
    hn = o0 * tanhf(cn);
}
__device__ __forceinline__ float2 h2f2(unsigned u) {
    __half2 h = *reinterpret_cast<__half2*>(&u);
    return __half22float2(h);
}
__device__ __forceinline__ __half2 u2h(unsigned u) {
    return *reinterpret_cast<__half2*>(&u);
}
__device__ __forceinline__ __half2 htanh2_add(unsigned q, unsigned k) {
    __half2 s = __hadd2(u2h(q), u2h(k));
    unsigned si = *reinterpret_cast<unsigned*>(&s);
    unsigned y;
    asm("tanh.approx.f16x2 %0, %1;" : "=r"(y) : "r"(si));
    return u2h(y);
}
__device__ __forceinline__ unsigned smem_u32(const void* p) {
    return (unsigned)__cvta_generic_to_shared(p);
}

#define LDSM4(r0, r1, r2, r3, addr) \
    asm volatile("ldmatrix.sync.aligned.m8n8.x4.shared.b16 {%0,%1,%2,%3}, [%4];" \
        : "=r"(r0), "=r"(r1), "=r"(r2), "=r"(r3) : "r"(addr))
#define LDSM4T(r0, r1, r2, r3, addr) \
    asm volatile("ldmatrix.sync.aligned.m8n8.x4.trans.shared.b16 {%0,%1,%2,%3}, [%4];" \
        : "=r"(r0), "=r"(r1), "=r"(r2), "=r"(r3) : "r"(addr))
#define MMA16816(c, a0, a1, a2, a3, b0, b1) \
    asm volatile("mma.sync.aligned.m16n8k16.row.col.f32.f16.f16.f32 " \
        "{%0,%1,%2,%3}, {%4,%5,%6,%7}, {%8,%9}, {%0,%1,%2,%3};" \
        : "+f"((c)[0]), "+f"((c)[1]), "+f"((c)[2]), "+f"((c)[3]) \
        : "r"(a0), "r"(a1), "r"(a2), "r"(a3), "r"(b0), "r"(b1))

// ---------------- HMMA 64x32 tile (fp16 inputs, fp32 accum) ----------------
template <class FA, class FB, class FE>
__device__ __forceinline__ void hmma_tile(float* shf, FA fA, FB fB, FE epi,
                                          int kbeg, int kend)
{
    __half* Ah = (__half*)shf;              // [64][40]
    __half* Bh = (__half*)shf + 64 * 40;    // [32][40]
    const int tid  = threadIdx.x;
    const int w    = tid >> 5;
    const int lane = tid & 31;

    float acc[4][4];
#pragma unroll
    for (int i = 0; i < 4; i++)
#pragma unroll
        for (int j = 0; j < 4; j++) acc[i][j] = 0.0f;

    const int am = tid >> 1;
    const int ak = (tid & 1) * 16;
    const int bk = tid >> 2;
    const int bc = (tid & 3) * 8;

    const int asel = (lane >> 4) * 8;
    const unsigned aBase = smem_u32(Ah + (16 * w + (lane & 15)) * 40 + asel);
    const unsigned bBase = smem_u32(Bh + (lane & 15) * 40 + asel);

    for (int k0 = kbeg; k0 < kend; k0 += 32) {
        __syncthreads();
        {
            float4 f0 = fA(am, k0 + ak);
            float4 f1 = fA(am, k0 + ak + 4);
            float4 f2 = fA(am, k0 + ak + 8);
            float4 f3 = fA(am, k0 + ak + 12);
            __half2 h0 = __floats2half2_rn(f0.x, f0.y);
            __half2 h1 = __floats2half2_rn(f0.z, f0.w);
            __half2 h2 = __floats2half2_rn(f1.x, f1.y);
            __half2 h3 = __floats2half2_rn(f1.z, f1.w);
            __half2 h4 = __floats2half2_rn(f2.x, f2.y);
            __half2 h5 = __floats2half2_rn(f2.z, f2.w);
            __half2 h6 = __floats2half2_rn(f3.x, f3.y);
            __half2 h7 = __floats2half2_rn(f3.z, f3.w);
            uint4 p0, p1;
            p0.x = *reinterpret_cast<unsigned*>(&h0);
            p0.y = *reinterpret_cast<unsigned*>(&h1);
            p0.z = *reinterpret_cast<unsigned*>(&h2);
            p0.w = *reinterpret_cast<unsigned*>(&h3);
            p1.x = *reinterpret_cast<unsigned*>(&h4);
            p1.y = *reinterpret_cast<unsigned*>(&h5);
            p1.z = *reinterpret_cast<unsigned*>(&h6);
            p1.w = *reinterpret_cast<unsigned*>(&h7);
            *(uint4*)(Ah + am * 40 + ak)     = p0;
            *(uint4*)(Ah + am * 40 + ak + 8) = p1;
        }
        *(uint4*)(Bh + bk * 40 + bc) = fB(k0 + bk, bc);
        __syncthreads();
#pragma unroll
        for (int s = 0; s < 2; s++) {
            unsigned a0, a1, a2, a3;
            LDSM4(a0, a1, a2, a3, aBase + s * 32);
#pragma unroll
            for (int nh = 0; nh < 2; nh++) {
                unsigned b0, b1, b2, b3;
                LDSM4T(b0, b1, b2, b3, bBase + s * 1280 + nh * 32);
                MMA16816(acc[2 * nh],     a0, a1, a2, a3, b0, b1);
                MMA16816(acc[2 * nh + 1], a0, a1, a2, a3, b2, b3);
            }
        }
    }
    const int r0 = 16 * w + (lane >> 2);
    const int c0 = (lane & 3) * 2;
#pragma unroll
    for (int nt = 0; nt < 4; nt++) {
        epi(r0,     nt * 8 + c0,     acc[nt][0]);
        epi(r0,     nt * 8 + c0 + 1, acc[nt][1]);
        epi(r0 + 8, nt * 8 + c0,     acc[nt][2]);
        epi(r0 + 8, nt * 8 + c0 + 1, acc[nt][3]);
    }
}

// ---------------- SIMT 64x32 fp32 tiled GEMM (output projection) ----------------
template <class FA, class FB, class FE>
__device__ __forceinline__ void gemm_tile(float* sh, FA fA, FB fB, FE epi,
                                          int kbeg, int kend)
{
    float* As = sh;
    float* Bs = sh + 2 * BK * ASTR;
    const int tid  = threadIdx.x;
    const int row0 = (tid >> 3) << 2;
    const int col0 = (tid & 7) << 2;
    const int lak  = (tid & 3) << 2;
    const int lam  = tid >> 2;
    const int lbk  = tid >> 3;
    const int lbn  = (tid & 7) << 2;

    float acc[4][4];
#pragma unroll
    for (int i = 0; i < 4; i++)
#pragma unroll
        for (int j = 0; j < 4; j++) acc[i][j] = 0.0f;

    const int nk = (kend - kbeg) >> 4;
    float4 ra0 = fA(lam,      kbeg + lak);
    float4 ra1 = fA(lam + 32, kbeg + lak);
    float4 rb  = fB(kbeg + lbk, lbn);

    __syncthreads();
    {
        float* Ad = As;
        Ad[(lak + 0) * ASTR + lam]      = ra0.x;
        Ad[(lak + 1) * ASTR + lam]      = ra0.y;
        Ad[(lak + 2) * ASTR + lam]      = ra0.z;
        Ad[(lak + 3) * ASTR + lam]      = ra0.w;
        Ad[(lak + 0) * ASTR + lam + 32] = ra1.x;
        Ad[(lak + 1) * ASTR + lam + 32] = ra1.y;
        Ad[(lak + 2) * ASTR + lam + 32] = ra1.z;
        Ad[(lak + 3) * ASTR + lam + 32] = ra1.w;
        *(float4*)&Bs[lbk * BN + lbn] = rb;
    }
    __syncthreads();

    int buf = 0;
    for (int kt = 0; kt < nk; kt++) {
        const bool more = (kt + 1 < nk);
        if (more) {
            int kk = kbeg + ((kt + 1) << 4);
            ra0 = fA(lam,      kk + lak);
            ra1 = fA(lam + 32, kk + lak);
            rb  = fB(kk + lbk, lbn);
        }
        const float* Ab = As + buf * (BK * ASTR);
        const float* Bb = Bs + buf * (BK * BN);
#pragma unroll
        for (int k = 0; k < BK; k++) {
            float4 av = *(const float4*)(Ab + k * ASTR + row0);
            float4 bv = *(const float4*)(Bb + k * BN  + col0);
            acc[0][0] += av.x * bv.x; acc[0][1] += av.x * bv.y;
            acc[0][2] += av.x * bv.z; acc[0][3] += av.x * bv.w;
            acc[1][0] += av.y * bv.x; acc[1][1] += av.y * bv.y;
            acc[1][2] += av.y * bv.z; acc[1][3] += av.y * bv.w;
            acc[2][0] += av.z * bv.x; acc[2][1] += av.z * bv.y;
            acc[2][2] += av.z * bv.z; acc[2][3] += av.z * bv.w;
            acc[3][0] += av.w * bv.x; acc[3][1] += av.w * bv.y;
            acc[3][2] += av.w * bv.z; acc[3][3] += av.w * bv.w;
        }
        if (more) {
            buf ^= 1;
            float* Ad = As + buf * (BK * ASTR);
            Ad[(lak + 0) * ASTR + lam]      = ra0.x;
            Ad[(lak + 1) * ASTR + lam]      = ra0.y;
            Ad[(lak + 2) * ASTR + lam]      = ra0.z;
            Ad[(lak + 3) * ASTR + lam]      = ra0.w;
            Ad[(lak + 0) * ASTR + lam + 32] = ra1.x;
            Ad[(lak + 1) * ASTR + lam + 32] = ra1.y;
            Ad[(lak + 2) * ASTR + lam + 32] = ra1.z;
            Ad[(lak + 3) * ASTR + lam + 32] = ra1.w;
            *(float4*)&Bs[buf * (BK * BN) + lbk * BN + lbn] = rb;
            __syncthreads();
        }
    }
    epi(row0, col0, acc);
}

// ---------------- persistent megakernel ----------------
__global__ void __launch_bounds__(NTH, 4) decoder_mega(
    const int*   __restrict__ tokens,
    const float* __restrict__ memory,
    const float* __restrict__ enc_h,
    const float* __restrict__ enc_c,
    const float* __restrict__ emb,
    const float* __restrict__ Wk,
    const float* __restrict__ Wr,
    const float* __restrict__ bias,
    const float* __restrict__ Wm,
    const float* __restrict__ Wq,
    const float* __restrict__ v,
    const float* __restrict__ Wa,
    const float* __restrict__ Wfc,
    const float* __restrict__ bfc,
    float*       __restrict__ out)
{
    __shared__ __align__(16) float sh[SH_FLOATS];
    const int tid = threadIdx.x;
    const int bid = blockIdx.x;

    auto lstm_chunk = [&](int tile, int kbeg, int kend, int t) {
        const int n0 = tile * BN;
        auto fA = [&](int m, int k) -> float4 {
            if (k < EE) {
                int tok = tokens[m * TT + t];
                return *(const float4*)(emb + (size_t)tok * EE + k);
            } else if (k < EE + UU) {
                return *(const float4*)(g_attn + m * UU + (k - EE));
            } else {
                return *(const float4*)(g_h + m * UU + (k - EE - UU));
            }
        };
        auto fB = [&](int k, int c8) -> uint4 {
            return *(const uint4*)(g_WkrH + (size_t)k * 4096 + n0 + c8);
        };
        auto epi = [&](int r, int c, float val) {
            atomicAdd(&g_z[r * (4 * UU) + n0 + c], val);
        };
        hmma_tile(sh, fA, fB, epi, kbeg, kend);
    };
    auto lstm_part1 = [&](int jj, int t) {
        const int tile  = jj & 127;
        const int chunk = jj >> 7;
        const int kb = (chunk == 0) ? 0 : (chunk == 1 ? 1536 : 2048);
        lstm_chunk(tile, kb, kb + 512, t);
    };

    // ---- Phase A: init state + fp16 conversions ----
    for (int b = bid; b < BB; b += NCTA) {
        int u = tid * 8;
#pragma unroll
        for (int half = 0; half < 2; half++) {
            int uu = u + half * 4;
            *(float4*)&g_h[b * UU + uu] = *(const float4*)(enc_h + b * UU + uu);
            *(float4*)&g_c[b * UU + uu] = *(const float4*)(enc_c + b * UU + uu);
            float4 z4 = make_float4(0.f, 0.f, 0.f, 0.f);
            *(float4*)&g_attn[b * UU + uu] = z4;
            *(float4*)&g_q[b * UU + uu]    = z4;
            *(float4*)&g_ctx[b * UU + uu]  = z4;
#pragma unroll
            for (int g = 0; g < 4; g++)
                *(float4*)&g_z[b * 4 * UU + g * UU + uu] = z4;
        }
    }
    {
        auto cvt8 = [&](const float* src, __half* dst) {
            float4 a = *(const float4*)(src);
            float4 b4 = *(const float4*)(src + 4);
            __half2 o0 = __floats2half2_rn(a.x, a.y);
            __half2 o1 = __floats2half2_rn(a.z, a.w);
            __half2 o2 = __floats2half2_rn(b4.x, b4.y);
            __half2 o3 = __floats2half2_rn(b4.z, b4.w);
            uint4 pk;
            pk.x = *reinterpret_cast<unsigned*>(&o0);
            pk.y = *reinterpret_cast<unsigned*>(&o1);
            pk.z = *reinterpret_cast<unsigned*>(&o2);
            pk.w = *reinterpret_cast<unsigned*>(&o3);
            *(uint4*)dst = pk;
        };
        const size_t gstride = (size_t)NCTA * NTH;
        const size_t gt = (size_t)bid * NTH + tid;
        for (size_t g = gt; g < (size_t)BB * SS * UU / 8; g += gstride)
            cvt8(memory + g * 8, g_memh + g * 8);
        for (size_t g = gt; g < (size_t)2560 * 4096 / 8; g += gstride) {
            size_t off = g * 8;
            const float* src = (off < (size_t)1536 * 4096) ? (Wk + off)
                                : (Wr + off - (size_t)1536 * 4096);
            cvt8(src, g_WkrH + off);
        }
        for (size_t g = gt; g < (size_t)1024 * 1024 / 8; g += gstride)
            cvt8(Wq + g * 8, g_WqH + g * 8);
        for (size_t g = gt; g < (size_t)2048 * 1024 / 8; g += gstride)
            cvt8(Wa + g * 8, g_WaH + g * 8);
        for (size_t g = gt; g < (size_t)1024 * 1024 / 8; g += gstride)
            cvt8(Wm + g * 8, g_WmH + g * 8);
    }
    grid_sync();

    // ---- Phase B: keys = fp16(memory @ Wm) via HMMA + lstm part1(t=0) ----
    {
        const int NK = 32768;
        const int NJ = NK + 384;
        const int per = (NJ + NCTA - 1) / NCTA;
        int j0 = bid * per;
        int j1 = j0 + per; if (j1 > NJ) j1 = NJ;
        for (int j = j0; j < j1; j++) {
            if (j < NK) {
                const int r0t = (j >> 5) * BM;
                const int n0 = (j & 31) * BN;
                auto fA = [&](int m, int k) -> float4 {
                    return *(const float4*)(memory + (size_t)(r0t + m) * UU + k);
                };
                auto fB = [&](int k, int c8) -> uint4 {
                    return *(const uint4*)(g_WmH + (size_t)k * UU + n0 + c8);
                };
                auto epi = [&](int r, int c, float val) {
                    g_keysh[(size_t)(r0t + r) * UU + n0 + c] = __float2half_rn(val);
                };
                hmma_tile(sh, fA, fB, epi, 0, UU);
            } else {
                lstm_part1(j - NK, 0);
            }
        }
    }
    grid_sync();

    // ================= decode loop =================
    for (int t = 0; t < TT; t++) {
        const bool more_t = (t + 1 < TT);

        // ---- P2: gates; zero z/q/attn/ctx; reset counters; bias-init out row t ----
        for (int b = bid; b < BB; b += NCTA) {
            int u = tid * 8;
            float* zb = g_z + b * 4 * UU;
            if (tid == 0) {
                g_sdone[b] = 0;
                if (b == 0) { g_qdone = 0; g_ctxdone = 0; g_attndone = 0; }
            }
#pragma unroll
            for (int half = 0; half < 2; half++) {
                int uu = u + half * 4;
                float4 zi = *(const float4*)(zb + uu);
                float4 zf = *(const float4*)(zb + UU + uu);
                float4 zg = *(const float4*)(zb + 2 * UU + uu);
                float4 zo = *(const float4*)(zb + 3 * UU + uu);
                float4 bi = *(const float4*)(bias + uu);
                float4 bf = *(const float4*)(bias + UU + uu);
                float4 bg = *(const float4*)(bias + 2 * UU + uu);
                float4 bo = *(const float4*)(bias + 3 * UU + uu);
                zi.x += bi.x; zi.y += bi.y; zi.z += bi.z; zi.w += bi.w;
                zf.x += bf.x; zf.y += bf.y; zf.z += bf.z; zf.w += bf.w;
                zg.x += bg.x; zg.y += bg.y; zg.z += bg.z; zg.w += bg.w;
                zo.x += bo.x; zo.y += bo.y; zo.z += bo.z; zo.w += bo.w;
                float4 c = *(const float4*)(g_c + b * UU + uu);
                float4 cn, hn;
                lstm_one(zi.x, zf.x, zg.x, zo.x, c.x, cn.x, hn.x);
                lstm_one(zi.y, zf.y, zg.y, zo.y, c.y, cn.y, hn.y);
                lstm_one(zi.z, zf.z, zg.z, zo.z, c.z, cn.z, hn.z);
                lstm_one(zi.w, zf.w, zg.w, zo.w, c.w, cn.w, hn.w);
                *(float4*)&g_c[b * UU + uu] = cn;
                *(float4*)&g_h[b * UU + uu] = hn;
                float4 z4 = make_float4(0.f, 0.f, 0.f, 0.f);
                *(float4*)(zb + uu)          = z4;
                *(float4*)(zb + UU + uu)     = z4;
                *(float4*)(zb + 2 * UU + uu) = z4;
                *(float4*)(zb + 3 * UU + uu) = z4;
                *(float4*)&g_q[b * UU + uu]    = z4;
                *(float4*)&g_attn[b * UU + uu] = z4;
                *(float4*)&g_ctx[b * UU + uu]  = z4;
                *(float4*)(out + ((size_t)b * TT + t) * VV + uu) = *(const float4*)(bfc + uu);
            }
        }
        grid_sync();

        // ---- FUSED: [lstm1 | attn1 | q | score | ctx | attn2 | out | lstm2] ----
        {
            bool qrdy = false, ctxrdy = false, attnrdy = false;
            for (int j = bid; j < F_END; j += NCTA) {
                if (j < F_A1) {
                    // ---- lstm1(t+1): dependency-free filler ----
                    if (more_t) lstm_part1(j, t + 1);
                } else if (j < F_Q) {
                    // ---- attn1 (h half of Wa): dependency-free filler ----
                    const int jj = j - F_A1;
                    const int n0 = (jj & 31) * BN;
                    const int kb = (jj >> 5) * 512;
                    auto fA = [&](int m, int k) -> float4 {
                        return *(const float4*)(g_h + m * UU + k);
                    };
                    auto fB = [&](int k, int c8) -> uint4 {
                        return *(const uint4*)(g_WaH + (size_t)k * UU + n0 + c8);
                    };
                    auto epi = [&](int r, int c, float val) {
                        atomicAdd(&g_attn[r * UU + n0 + c], val);
                    };
                    hmma_tile(sh, fA, fB, epi, kb, kb + 512);
                    publish(&g_attndone);
                } else if (j < F_SC) {
                    // ---- q job ----
                    const int jj = j - F_Q;
                    const int n0 = (jj & 31) * BN;
                    const int kb = (jj >> 5) * 512;
                    auto fA = [&](int m, int k) -> float4 {
                        return *(const float4*)(g_h + m * UU + k);
                    };
                    auto fB = [&](int k, int c8) -> uint4 {
                        return *(const uint4*)(g_WqH + (size_t)k * UU + n0 + c8);
                    };
                    auto epi = [&](int r, int c, float val) {
                        atomicAdd(&g_q[r * UU + n0 + c], val);
                    };
                    hmma_tile(sh, fA, fB, epi, kb, kb + 512);
                    publish(&g_qdone);
                } else if (j < F_CTX) {
                    // ---- score job ----
                    if (!qrdy) { wait_ctr(&g_qdone, 64u); qrdy = true; }
                    const int js = j - F_SC;
                    const int b  = js >> 6;
                    const int s0 = (js & 63) << 4;
                    __half* qs2 = (__half*)sh;
                    __half* vs2 = (__half*)sh + 1024;
                    __syncthreads();
                    {
                        int u = tid * 8;
                        float4 a  = *(const float4*)(g_q + b * UU + u);
                        float4 b4 = *(const float4*)(g_q + b * UU + u + 4);
                        __half2 h0 = __floats2half2_rn(a.x, a.y);
                        __half2 h1 = __floats2half2_rn(a.z, a.w);
                        __half2 h2 = __floats2half2_rn(b4.x, b4.y);
                        __half2 h3 = __floats2half2_rn(b4.z, b4.w);
                        uint4 pk;
                        pk.x = *reinterpret_cast<unsigned*>(&h0);
                        pk.y = *reinterpret_cast<unsigned*>(&h1);
                        pk.z = *reinterpret_cast<unsigned*>(&h2);
                        pk.w = *reinterpret_cast<unsigned*>(&h3);
                        *(uint4*)(qs2 + u) = pk;
                        float4 va  = *(const float4*)(v + u);
                        float4 vb4 = *(const float4*)(v + u + 4);
                        __half2 g0 = __floats2half2_rn(va.x, va.y);
                        __half2 g1 = __floats2half2_rn(va.z, va.w);
                        __half2 g2 = __floats2half2_rn(vb4.x, vb4.y);
                        __half2 g3 = __floats2half2_rn(vb4.z, vb4.w);
                        uint4 pv;
                        pv.x = *reinterpret_cast<unsigned*>(&g0);
                        pv.y = *reinterpret_cast<unsigned*>(&g1);
                        pv.z = *reinterpret_cast<unsigned*>(&g2);
                        pv.w = *reinterpret_cast<unsigned*>(&g3);
                        *(uint4*)(vs2 + u) = pv;
                    }
                    __syncthreads();
                    const int w = tid >> 5, lane = tid & 31;
                    const int sbase = s0 + w * 4;
                    const __half* kr = g_keysh + ((size_t)b * SS + sbase) * UU;
                    float p[4] = {0.f, 0.f, 0.f, 0.f};
#pragma unroll
                    for (int it = 0; it < 4; it++) {
                        int u = it * 256 + lane * 8;
                        uint4 q4 = *(const uint4*)(qs2 + u);
                        uint4 v4 = *(const uint4*)(vs2 + u);
#pragma unroll
                        for (int r = 0; r < 4; r++) {
                            uint4 raw = *(const uint4*)(kr + (size_t)r * UU + u);
                            __half2 t0 = htanh2_add(q4.x, raw.x);
                            __half2 t1 = htanh2_add(q4.y, raw.y);
                            __half2 t2 = htanh2_add(q4.z, raw.z);
                            __half2 t3 = htanh2_add(q4.w, raw.w);
                            __half2 acc2 = __hmul2(u2h(v4.x), t0);
                            acc2 = __hfma2(u2h(v4.y), t1, acc2);
                            acc2 = __hfma2(u2h(v4.z), t2, acc2);
                            acc2 = __hfma2(u2h(v4.w), t3, acc2);
                            float2 pf = __half22float2(acc2);
                            p[r] += pf.x + pf.y;
                        }
                    }
#pragma unroll
                    for (int r = 0; r < 4; r++) {
#pragma unroll
                        for (int o = 16; o; o >>= 1)
                            p[r] += __shfl_xor_sync(0xFFFFFFFFu, p[r], o);
                    }
                    if (lane == 0) {
#pragma unroll
                        for (int r = 0; r < 4; r++)
                            g_score[b * SS + sbase + r] = p[r];
                    }
                    publish(&g_sdone[b]);
                } else if (j < F_A2) {
                    // ---- ctx job (waits for its row's 64 score jobs) ----
                    const int jj  = j - F_CTX;
                    const int b   = jj >> 3;
                    const int sc0 = (jj & 7) * 128;
                    wait_ctr(&g_sdone[b], 64u);
                    const int w = tid >> 5, lane = tid & 31;
                    float* red = sh;
                    float* wal = sh + 16;
                    float s8[8];
                    {
                        float4 a  = *(const float4*)(g_score + b * SS + tid * 8);
                        float4 b4 = *(const float4*)(g_score + b * SS + tid * 8 + 4);
                        s8[0]=a.x; s8[1]=a.y; s8[2]=a.z; s8[3]=a.w;
                        s8[4]=b4.x; s8[5]=b4.y; s8[6]=b4.z; s8[7]=b4.w;
                    }
                    float mx = s8[0];
#pragma unroll
                    for (int i = 1; i < 8; i++) mx = fmaxf(mx, s8[i]);
#pragma unroll
                    for (int o = 16; o; o >>= 1) mx = fmaxf(mx, __shfl_xor_sync(0xFFFFFFFFu, mx, o));
                    __syncthreads();
                    if (lane == 0) red[w] = mx;
                    __syncthreads();
                    mx = fmaxf(fmaxf(red[0], red[1]), fmaxf(red[2], red[3]));
                    float e8[8], lsum = 0.f;
#pragma unroll
                    for (int i = 0; i < 8; i++) { e8[i] = __expf(s8[i] - mx); lsum += e8[i]; }
#pragma unroll
                    for (int o = 16; o; o >>= 1) lsum += __shfl_xor_sync(0xFFFFFFFFu, lsum, o);
                    __syncthreads();
                    if (lane == 0) red[4 + w] = lsum;
                    __syncthreads();
                    float inv = 1.0f / (red[4] + red[5] + red[6] + red[7]);
                    {
                        int p0 = tid * 8;
                        if (p0 >= sc0 && p0 < sc0 + 128) {
#pragma unroll
                            for (int i = 0; i < 8; i++) wal[p0 - sc0 + i] = e8[i] * inv;
                        }
                    }
                    __syncthreads();
                    const int u0 = tid * 8;
                    const __half* mp = g_memh + ((size_t)b * SS + sc0) * UU + u0;
                    float4 a0 = make_float4(0.f, 0.f, 0.f, 0.f);
                    float4 a1 = make_float4(0.f, 0.f, 0.f, 0.f);
#pragma unroll 4
                    for (int s = 0; s < 128; s++) {
                        float wv = wal[s];
                        uint4 raw = *(const uint4*)(mp + (size_t)s * UU);
                        float2 f0 = h2f2(raw.x);
                        float2 f1 = h2f2(raw.y);
                        float2 f2 = h2f2(raw.z);
                        float2 f3 = h2f2(raw.w);
                        a0.x += wv * f0.x; a0.y += wv * f0.y;
                        a0.z += wv * f1.x; a0.w += wv * f1.y;
                        a1.x += wv * f2.x; a1.y += wv * f2.y;
                        a1.z += wv * f3.x; a1.w += wv * f3.y;
                    }
                    float* cp = g_ctx + b * UU + u0;
                    atomicAdd(cp + 0, a0.x); atomicAdd(cp + 1, a0.y);
                    atomicAdd(cp + 2, a0.z); atomicAdd(cp + 3, a0.w);
                    atomicAdd(cp + 4, a1.x); atomicAdd(cp + 5, a1.y);
                    atomicAdd(cp + 6, a1.z); atomicAdd(cp + 7, a1.w);
                    publish(&g_ctxdone);
                } else if (j < F_OUT) {
                    // ---- attn2 job (ctx cols of Wa; waits all ctx) ----
                    if (!ctxrdy) { wait_ctr(&g_ctxdone, 512u); ctxrdy = true; }
                    const int jj = j - F_A2;
                    const int n0 = (jj & 31) * BN;
                    const int kb = 1024 + (jj >> 5) * 256;
                    auto fA = [&](int m, int k) -> float4 {
                        return *(const float4*)(g_ctx + m * UU + (k - 1024));
                    };
                    auto fB = [&](int k, int c8) -> uint4 {
                        return *(const uint4*)(g_WaH + (size_t)k * UU + n0 + c8);
                    };
                    auto epi = [&](int r, int c, float val) {
                        atomicAdd(&g_attn[r * UU + n0 + c], val);
                    };
                    hmma_tile(sh, fA, fB, epi, kb, kb + 256);
                    publish(&g_attndone);
                } else if (j < F_L2) {
                    // ---- out job (waits attn complete: 64 attn1 + 128 attn2) ----
                    if (!attnrdy) { wait_ctr(&g_attndone, 192u); attnrdy = true; }
                    const int jj = j - F_OUT;
                    const int n0 = (jj & 31) * BN;
                    const int kb = (jj >> 5) * 128;
                    auto fA = [&](int m, int k) -> float4 {
                        return *(const float4*)(g_attn + m * UU + k);
                    };
                    auto fB = [&](int k, int nr) -> float4 {
                        return *(const float4*)(Wfc + (size_t)k * VV + n0 + nr);
                    };
                    auto epi = [&](int r, int c, float (&acc)[4][4]) {
#pragma unroll
                        for (int i = 0; i < 4; i++) {
                            float* dst = out + ((size_t)(r + i) * TT + t) * VV + n0 + c;
#pragma unroll
                            for (int jj2 = 0; jj2 < 4; jj2++) atomicAdd(dst + jj2, acc[i][jj2]);
                        }
                    };
                    gemm_tile(sh, fA, fB, epi, kb, kb + 128);
                } else {
                    // ---- lstm2(t+1) job (reads attn) ----
                    if (more_t) {
                        if (!attnrdy) { wait_ctr(&g_attndone, 192u); attnrdy = true; }
                        const int jj = j - F_L2;
                        const int tile = jj & 127;
                        const int kb = 512 + (jj >> 7) * 512;
                        lstm_chunk(tile, kb, kb + 512, t + 1);
                    }
                }
            }
        }
        grid_sync();
    }
}

// ---------------- host launcher: ONE graph node ----------------
extern "C" void kernel_launch(void* const* d_in, const int* in_sizes, int n_in,
                              void* d_out, int out_size)
{
    const int*   tokens = (const int*)  d_in[0];
    const float* memory = (const float*)d_in[1];
    const float* enc_h  = (const float*)d_in[2];
    const float* enc_c  = (const float*)d_in[3];
    const float* emb    = (const float*)d_in[4];
    const float* Wk     = (const float*)d_in[5];
    const float* Wr     = (const float*)d_in[6];
    const float* bias   = (const float*)d_in[7];
    const float* Wm     = (const float*)d_in[8];
    const float* Wq     = (const float*)d_in[9];
    const float* v      = (const float*)d_in[10];
    const float* Wa     = (const float*)d_in[11];
    const float* Wfc    = (const float*)d_in[12];
    const float* bfc    = (const float*)d_in[13];
    float* out = (float*)d_out;

    decoder_mega<<<NCTA, NTH>>>(tokens, memory, enc_h, enc_c, emb, Wk, Wr, bias,
                                Wm, Wq, v, Wa, Wfc, bfc, out);
}

// round 17
// speedup vs baseline: 1.0725x; 1.0725x over previous
#include <cuda_runtime.h>
#include <cuda_fp16.h>
#include <math.h>

#define BB 64
#define SS 1024
#define TT 511
#define VV 1024
#define EE 512
#define UU 1024

#define NCTA 592
#define NTH  128

#define BM 64
#define BN 32
#define SH_FLOATS 3200   // 12.8 KB

// fused-phase job ranges: [lstm1 | attn1 | q | score | ctx]
#define F_A1   384     // lstm1: [0,384)
#define F_Q    448     // attn1: [384,448)
#define F_SC   512     // q:     [448,512)
#define F_CTX  4608    // score: [512,4608)
#define F_END  5120    // ctx:   [4608,5120)

// ---------------- device scratch ----------------
__device__ __align__(16) __half g_keysh[(size_t)BB * SS * UU];  // 128 MB
__device__ __align__(16) __half g_memh[(size_t)BB * SS * UU];   // 128 MB
__device__ __align__(16) __half g_WkrH[(size_t)2560 * 4096];    // 21 MB
__device__ __align__(16) __half g_WqH[1024 * 1024];
__device__ __align__(16) __half g_WaH[2048 * 1024];
__device__ __align__(16) __half g_WmH[1024 * 1024];
__device__ __align__(16) __half g_WfcH[1024 * 1024];
__device__ __align__(16) float g_z[BB * 4 * UU];
__device__ __align__(16) float g_h[BB * UU];
__device__ __align__(16) float g_c[BB * UU];
__device__ __align__(16) float g_attn[BB * UU];
__device__ __align__(16) float g_q[BB * UU];
__device__ __align__(16) float g_score[BB * SS];
__device__ __align__(16) float g_ctx[BB * UU];
__device__ unsigned g_sdone[BB];
__device__ unsigned g_qdone = 0;

// ---------------- grid barrier ----------------
__device__ unsigned g_bar_cnt = 0;
__device__ volatile unsigned g_bar_gen = 0;

__device__ __forceinline__ void grid_sync() {
    __syncthreads();
    __threadfence();
    if (threadIdx.x == 0) {
        unsigned gen = g_bar_gen;
        if (atomicAdd(&g_bar_cnt, 1u) == NCTA - 1u) {
            g_bar_cnt = 0;
            __threadfence();
            g_bar_gen = gen + 1u;
        } else {
            while (g_bar_gen == gen) { }
        }
    }
    __syncthreads();
}

// publish: CTA-wide fence then bump counter
__device__ __forceinline__ void publish(unsigned* ctr) {
    __threadfence();
    __syncthreads();
    if (threadIdx.x == 0) atomicAdd(ctr, 1u);
}
// acquire: spin until counter reaches target, then flush L1
__device__ __forceinline__ void wait_ctr(unsigned* ctr, unsigned target) {
    if (threadIdx.x == 0) {
        while (atomicAdd(ctr, 0u) < target) { }
    }
    __syncthreads();
    __threadfence();
}

// ---------------- math helpers ----------------
__device__ __forceinline__ float sigmoid_acc(float x) {
    return 1.0f / (1.0f + expf(-x));
}
__device__ __forceinline__ void lstm_one(float zi, float zf, float zg, float zo,
                                         float c, float& cn, float& hn) {
    float i0 = sigmoid_acc(zi);
    float f0 = sigmoid_acc(zf);
    float g0 = tanhf(zg);
    float o0 = sigmoid_acc(zo);
    cn = f0 * c + i0 * g0;
    hn = o0 * tanhf(cn);
}
__device__ __forceinline__ float2 h2f2(unsigned u) {
    __half2 h = *reinterpret_cast<__half2*>(&u);
    return __half22float2(h);
}
__device__ __forceinline__ __half2 u2h(unsigned u) {
    return *reinterpret_cast<__half2*>(&u);
}
__device__ __forceinline__ __half2 htanh2_add(unsigned q, unsigned k) {
    __half2 s = __hadd2(u2h(q), u2h(k));
    unsigned si = *reinterpret_cast<unsigned*>(&s);
    unsigned y;
    asm("tanh.approx.f16x2 %0, %1;" : "=r"(y) : "r"(si));
    return u2h(y);
}
__device__ __forceinline__ unsigned smem_u32(const void* p) {
    return (unsigned)__cvta_generic_to_shared(p);
}

#define LDSM4(r0, r1, r2, r3, addr) \
    asm volatile("ldmatrix.sync.aligned.m8n8.x4.shared.b16 {%0,%1,%2,%3}, [%4];" \
        : "=r"(r0), "=r"(r1), "=r"(r2), "=r"(r3) : "r"(addr))
#define LDSM4T(r0, r1, r2, r3, addr) \
    asm volatile("ldmatrix.sync.aligned.m8n8.x4.trans.shared.b16 {%0,%1,%2,%3}, [%4];" \
        : "=r"(r0), "=r"(r1), "=r"(r2), "=r"(r3) : "r"(addr))
#define MMA16816(c, a0, a1, a2, a3, b0, b1) \
    asm volatile("mma.sync.aligned.m16n8k16.row.col.f32.f16.f16.f32 " \
        "{%0,%1,%2,%3}, {%4,%5,%6,%7}, {%8,%9}, {%0,%1,%2,%3};" \
        : "+f"((c)[0]), "+f"((c)[1]), "+f"((c)[2]), "+f"((c)[3]) \
        : "r"(a0), "r"(a1), "r"(a2), "r"(a3), "r"(b0), "r"(b1))

// ---------------- HMMA 64x32 tile (fp16 inputs, fp32 accum) ----------------
template <class FA, class FB, class FE>
__device__ __forceinline__ void hmma_tile(float* shf, FA fA, FB fB, FE epi,
                                          int kbeg, int kend)
{
    __half* Ah = (__half*)shf;              // [64][40]
    __half* Bh = (__half*)shf + 64 * 40;    // [32][40]
    const int tid  = threadIdx.x;
    const int w    = tid >> 5;
    const int lane = tid & 31;

    float acc[4][4];
#pragma unroll
    for (int i = 0; i < 4; i++)
#pragma unroll
        for (int j = 0; j < 4; j++) acc[i][j] = 0.0f;

    const int am = tid >> 1;
    const int ak = (tid & 1) * 16;
    const int bk = tid >> 2;
    const int bc = (tid & 3) * 8;

    const int asel = (lane >> 4) * 8;
    const unsigned aBase = smem_u32(Ah + (16 * w + (lane & 15)) * 40 + asel);
    const unsigned bBase = smem_u32(Bh + (lane & 15) * 40 + asel);

    for (int k0 = kbeg; k0 < kend; k0 += 32) {
        __syncthreads();
        {
            float4 f0 = fA(am, k0 + ak);
            float4 f1 = fA(am, k0 + ak + 4);
            float4 f2 = fA(am, k0 + ak + 8);
            float4 f3 = fA(am, k0 + ak + 12);
            __half2 h0 = __floats2half2_rn(f0.x, f0.y);
            __half2 h1 = __floats2half2_rn(f0.z, f0.w);
            __half2 h2 = __floats2half2_rn(f1.x, f1.y);
            __half2 h3 = __floats2half2_rn(f1.z, f1.w);
            __half2 h4 = __floats2half2_rn(f2.x, f2.y);
            __half2 h5 = __floats2half2_rn(f2.z, f2.w);
            __half2 h6 = __floats2half2_rn(f3.x, f3.y);
            __half2 h7 = __floats2half2_rn(f3.z, f3.w);
            uint4 p0, p1;
            p0.x = *reinterpret_cast<unsigned*>(&h0);
            p0.y = *reinterpret_cast<unsigned*>(&h1);
            p0.z = *reinterpret_cast<unsigned*>(&h2);
            p0.w = *reinterpret_cast<unsigned*>(&h3);
            p1.x = *reinterpret_cast<unsigned*>(&h4);
            p1.y = *reinterpret_cast<unsigned*>(&h5);
            p1.z = *reinterpret_cast<unsigned*>(&h6);
            p1.w = *reinterpret_cast<unsigned*>(&h7);
            *(uint4*)(Ah + am * 40 + ak)     = p0;
            *(uint4*)(Ah + am * 40 + ak + 8) = p1;
        }
        *(uint4*)(Bh + bk * 40 + bc) = fB(k0 + bk, bc);
        __syncthreads();
#pragma unroll
        for (int s = 0; s < 2; s++) {
            unsigned a0, a1, a2, a3;
            LDSM4(a0, a1, a2, a3, aBase + s * 32);
#pragma unroll
            for (int nh = 0; nh < 2; nh++) {
                unsigned b0, b1, b2, b3;
                LDSM4T(b0, b1, b2, b3, bBase + s * 1280 + nh * 32);
                MMA16816(acc[2 * nh],     a0, a1, a2, a3, b0, b1);
                MMA16816(acc[2 * nh + 1], a0, a1, a2, a3, b2, b3);
            }
        }
    }
    const int r0 = 16 * w + (lane >> 2);
    const int c0 = (lane & 3) * 2;
#pragma unroll
    for (int nt = 0; nt < 4; nt++) {
        epi(r0,     nt * 8 + c0,     acc[nt][0]);
        epi(r0,     nt * 8 + c0 + 1, acc[nt][1]);
        epi(r0 + 8, nt * 8 + c0,     acc[nt][2]);
        epi(r0 + 8, nt * 8 + c0 + 1, acc[nt][3]);
    }
}

// ---------------- persistent megakernel ----------------
__global__ void __launch_bounds__(NTH, 4) decoder_mega(
    const int*   __restrict__ tokens,
    const float* __restrict__ memory,
    const float* __restrict__ enc_h,
    const float* __restrict__ enc_c,
    const float* __restrict__ emb,
    const float* __restrict__ Wk,
    const float* __restrict__ Wr,
    const float* __restrict__ bias,
    const float* __restrict__ Wm,
    const float* __restrict__ Wq,
    const float* __restrict__ v,
    const float* __restrict__ Wa,
    const float* __restrict__ Wfc,
    const float* __restrict__ bfc,
    float*       __restrict__ out)
{
    __shared__ __align__(16) float sh[SH_FLOATS];
    const int tid = threadIdx.x;
    const int bid = blockIdx.x;

    auto lstm_chunk = [&](int tile, int kbeg, int kend, int t) {
        const int n0 = tile * BN;
        auto fA = [&](int m, int k) -> float4 {
            if (k < EE) {
                int tok = tokens[m * TT + t];
                return *(const float4*)(emb + (size_t)tok * EE + k);
            } else if (k < EE + UU) {
                return *(const float4*)(g_attn + m * UU + (k - EE));
            } else {
                return *(const float4*)(g_h + m * UU + (k - EE - UU));
            }
        };
        auto fB = [&](int k, int c8) -> uint4 {
            return *(const uint4*)(g_WkrH + (size_t)k * 4096 + n0 + c8);
        };
        auto epi = [&](int r, int c, float val) {
            atomicAdd(&g_z[r * (4 * UU) + n0 + c], val);
        };
        hmma_tile(sh, fA, fB, epi, kbeg, kend);
    };
    auto lstm_part1 = [&](int jj, int t) {
        const int tile  = jj & 127;
        const int chunk = jj >> 7;
        const int kb = (chunk == 0) ? 0 : (chunk == 1 ? 1536 : 2048);
        lstm_chunk(tile, kb, kb + 512, t);
    };

    // ---- Phase A: init state + fp16 conversions ----
    for (int b = bid; b < BB; b += NCTA) {
        int u = tid * 8;
#pragma unroll
        for (int half = 0; half < 2; half++) {
            int uu = u + half * 4;
            *(float4*)&g_h[b * UU + uu] = *(const float4*)(enc_h + b * UU + uu);
            *(float4*)&g_c[b * UU + uu] = *(const float4*)(enc_c + b * UU + uu);
            float4 z4 = make_float4(0.f, 0.f, 0.f, 0.f);
            *(float4*)&g_attn[b * UU + uu] = z4;
            *(float4*)&g_q[b * UU + uu]    = z4;
            *(float4*)&g_ctx[b * UU + uu]  = z4;
#pragma unroll
            for (int g = 0; g < 4; g++)
                *(float4*)&g_z[b * 4 * UU + g * UU + uu] = z4;
        }
    }
    {
        auto cvt8 = [&](const float* src, __half* dst) {
            float4 a = *(const float4*)(src);
            float4 b4 = *(const float4*)(src + 4);
            __half2 o0 = __floats2half2_rn(a.x, a.y);
            __half2 o1 = __floats2half2_rn(a.z, a.w);
            __half2 o2 = __floats2half2_rn(b4.x, b4.y);
            __half2 o3 = __floats2half2_rn(b4.z, b4.w);
            uint4 pk;
            pk.x = *reinterpret_cast<unsigned*>(&o0);
            pk.y = *reinterpret_cast<unsigned*>(&o1);
            pk.z = *reinterpret_cast<unsigned*>(&o2);
            pk.w = *reinterpret_cast<unsigned*>(&o3);
            *(uint4*)dst = pk;
        };
        const size_t gstride = (size_t)NCTA * NTH;
        const size_t gt = (size_t)bid * NTH + tid;
        for (size_t g = gt; g < (size_t)BB * SS * UU / 8; g += gstride)
            cvt8(memory + g * 8, g_memh + g * 8);
        for (size_t g = gt; g < (size_t)2560 * 4096 / 8; g += gstride) {
            size_t off = g * 8;
            const float* src = (off < (size_t)1536 * 4096) ? (Wk + off)
                                : (Wr + off - (size_t)1536 * 4096);
            cvt8(src, g_WkrH + off);
        }
        for (size_t g = gt; g < (size_t)1024 * 1024 / 8; g += gstride)
            cvt8(Wq + g * 8, g_WqH + g * 8);
        for (size_t g = gt; g < (size_t)2048 * 1024 / 8; g += gstride)
            cvt8(Wa + g * 8, g_WaH + g * 8);
        for (size_t g = gt; g < (size_t)1024 * 1024 / 8; g += gstride)
            cvt8(Wm + g * 8, g_WmH + g * 8);
        for (size_t g = gt; g < (size_t)1024 * 1024 / 8; g += gstride)
            cvt8(Wfc + g * 8, g_WfcH + g * 8);
    }
    grid_sync();

    // ---- Phase B: keys = fp16(memory @ Wm) via HMMA + lstm part1(t=0) ----
    {
        const int NK = 32768;
        const int NJ = NK + 384;
        const int per = (NJ + NCTA - 1) / NCTA;
        int j0 = bid * per;
        int j1 = j0 + per; if (j1 > NJ) j1 = NJ;
        for (int j = j0; j < j1; j++) {
            if (j < NK) {
                const int r0t = (j >> 5) * BM;
                const int n0 = (j & 31) * BN;
                auto fA = [&](int m, int k) -> float4 {
                    return *(const float4*)(memory + (size_t)(r0t + m) * UU + k);
                };
                auto fB = [&](int k, int c8) -> uint4 {
                    return *(const uint4*)(g_WmH + (size_t)k * UU + n0 + c8);
                };
                auto epi = [&](int r, int c, float val) {
                    g_keysh[(size_t)(r0t + r) * UU + n0 + c] = __float2half_rn(val);
                };
                hmma_tile(sh, fA, fB, epi, 0, UU);
            } else {
                lstm_part1(j - NK, 0);
            }
        }
    }
    grid_sync();

    // ================= decode loop =================
    for (int t = 0; t < TT; t++) {
        const bool more_t = (t + 1 < TT);

        // ---- P2: gates; zero z/q/attn/ctx; reset counters; bias-init out row t ----
        for (int b = bid; b < BB; b += NCTA) {
            int u = tid * 8;
            float* zb = g_z + b * 4 * UU;
            if (tid == 0) {
                g_sdone[b] = 0;
                if (b == 0) g_qdone = 0;
            }
#pragma unroll
            for (int half = 0; half < 2; half++) {
                int uu = u + half * 4;
                float4 zi = *(const float4*)(zb + uu);
                float4 zf = *(const float4*)(zb + UU + uu);
                float4 zg = *(const float4*)(zb + 2 * UU + uu);
                float4 zo = *(const float4*)(zb + 3 * UU + uu);
                float4 bi = *(const float4*)(bias + uu);
                float4 bf = *(const float4*)(bias + UU + uu);
                float4 bg = *(const float4*)(bias + 2 * UU + uu);
                float4 bo = *(const float4*)(bias + 3 * UU + uu);
                zi.x += bi.x; zi.y += bi.y; zi.z += bi.z; zi.w += bi.w;
                zf.x += bf.x; zf.y += bf.y; zf.z += bf.z; zf.w += bf.w;
                zg.x += bg.x; zg.y += bg.y; zg.z += bg.z; zg.w += bg.w;
                zo.x += bo.x; zo.y += bo.y; zo.z += bo.z; zo.w += bo.w;
                float4 c = *(const float4*)(g_c + b * UU + uu);
                float4 cn, hn;
                lstm_one(zi.x, zf.x, zg.x, zo.x, c.x, cn.x, hn.x);
                lstm_one(zi.y, zf.y, zg.y, zo.y, c.y, cn.y, hn.y);
                lstm_one(zi.z, zf.z, zg.z, zo.z, c.z, cn.z, hn.z);
                lstm_one(zi.w, zf.w, zg.w, zo.w, c.w, cn.w, hn.w);
                *(float4*)&g_c[b * UU + uu] = cn;
                *(float4*)&g_h[b * UU + uu] = hn;
                float4 z4 = make_float4(0.f, 0.f, 0.f, 0.f);
                *(float4*)(zb + uu)          = z4;
                *(float4*)(zb + UU + uu)     = z4;
                *(float4*)(zb + 2 * UU + uu) = z4;
                *(float4*)(zb + 3 * UU + uu) = z4;
                *(float4*)&g_q[b * UU + uu]    = z4;
                *(float4*)&g_attn[b * UU + uu] = z4;
                *(float4*)&g_ctx[b * UU + uu]  = z4;
                *(float4*)(out + ((size_t)b * TT + t) * VV + uu) = *(const float4*)(bfc + uu);
            }
        }
        grid_sync();

        // ---- FUSED: [lstm1 | attn1 | q | score | ctx] with counter sync ----
        {
            bool qrdy = false;
            for (int j = bid; j < F_END; j += NCTA) {
                if (j < F_A1) {
                    if (more_t) lstm_part1(j, t + 1);
                } else if (j < F_Q) {
                    const int jj = j - F_A1;
                    const int n0 = (jj & 31) * BN;
                    const int kb = (jj >> 5) * 512;
                    auto fA = [&](int m, int k) -> float4 {
                        return *(const float4*)(g_h + m * UU + k);
                    };
                    auto fB = [&](int k, int c8) -> uint4 {
                        return *(const uint4*)(g_WaH + (size_t)k * UU + n0 + c8);
                    };
                    auto epi = [&](int r, int c, float val) {
                        atomicAdd(&g_attn[r * UU + n0 + c], val);
                    };
                    hmma_tile(sh, fA, fB, epi, kb, kb + 512);
                } else if (j < F_SC) {
                    const int jj = j - F_Q;
                    const int n0 = (jj & 31) * BN;
                    const int kb = (jj >> 5) * 512;
                    auto fA = [&](int m, int k) -> float4 {
                        return *(const float4*)(g_h + m * UU + k);
                    };
                    auto fB = [&](int k, int c8) -> uint4 {
                        return *(const uint4*)(g_WqH + (size_t)k * UU + n0 + c8);
                    };
                    auto epi = [&](int r, int c, float val) {
                        atomicAdd(&g_q[r * UU + n0 + c], val);
                    };
                    hmma_tile(sh, fA, fB, epi, kb, kb + 512);
                    publish(&g_qdone);
                } else if (j < F_CTX) {
                    if (!qrdy) { wait_ctr(&g_qdone, 64u); qrdy = true; }
                    const int js = j - F_SC;
                    const int b  = js >> 6;
                    const int s0 = (js & 63) << 4;
                    __half* qs2 = (__half*)sh;
                    __half* vs2 = (__half*)sh + 1024;
                    __syncthreads();
                    {
                        int u = tid * 8;
                        float4 a  = *(const float4*)(g_q + b * UU + u);
                        float4 b4 = *(const float4*)(g_q + b * UU + u + 4);
                        __half2 h0 = __floats2half2_rn(a.x, a.y);
                        __half2 h1 = __floats2half2_rn(a.z, a.w);
                        __half2 h2 = __floats2half2_rn(b4.x, b4.y);
                        __half2 h3 = __floats2half2_rn(b4.z, b4.w);
                        uint4 pk;
                        pk.x = *reinterpret_cast<unsigned*>(&h0);
                        pk.y = *reinterpret_cast<unsigned*>(&h1);
                        pk.z = *reinterpret_cast<unsigned*>(&h2);
                        pk.w = *reinterpret_cast<unsigned*>(&h3);
                        *(uint4*)(qs2 + u) = pk;
                        float4 va  = *(const float4*)(v + u);
                        float4 vb4 = *(const float4*)(v + u + 4);
                        __half2 g0 = __floats2half2_rn(va.x, va.y);
                        __half2 g1 = __floats2half2_rn(va.z, va.w);
                        __half2 g2 = __floats2half2_rn(vb4.x, vb4.y);
                        __half2 g3 = __floats2half2_rn(vb4.z, vb4.w);
                        uint4 pv;
                        pv.x = *reinterpret_cast<unsigned*>(&g0);
                        pv.y = *reinterpret_cast<unsigned*>(&g1);
                        pv.z = *reinterpret_cast<unsigned*>(&g2);
                        pv.w = *reinterpret_cast<unsigned*>(&g3);
                        *(uint4*)(vs2 + u) = pv;
                    }
                    __syncthreads();
                    const int w = tid >> 5, lane = tid & 31;
                    const int sbase = s0 + w * 4;
                    const __half* kr = g_keysh + ((size_t)b * SS + sbase) * UU;
                    float p[4] = {0.f, 0.f, 0.f, 0.f};
#pragma unroll
                    for (int it = 0; it < 4; it++) {
                        int u = it * 256 + lane * 8;
                        uint4 q4 = *(const uint4*)(qs2 + u);
                        uint4 v4 = *(const uint4*)(vs2 + u);
#pragma unroll
                        for (int r = 0; r < 4; r++) {
                            uint4 raw = *(const uint4*)(kr + (size_t)r * UU + u);
                            __half2 t0 = htanh2_add(q4.x, raw.x);
                            __half2 t1 = htanh2_add(q4.y, raw.y);
                            __half2 t2 = htanh2_add(q4.z, raw.z);
                            __half2 t3 = htanh2_add(q4.w, raw.w);
                            __half2 acc2 = __hmul2(u2h(v4.x), t0);
                            acc2 = __hfma2(u2h(v4.y), t1, acc2);
                            acc2 = __hfma2(u2h(v4.z), t2, acc2);
                            acc2 = __hfma2(u2h(v4.w), t3, acc2);
                            float2 pf = __half22float2(acc2);
                            p[r] += pf.x + pf.y;
                        }
                    }
#pragma unroll
                    for (int r = 0; r < 4; r++) {
#pragma unroll
                        for (int o = 16; o; o >>= 1)
                            p[r] += __shfl_xor_sync(0xFFFFFFFFu, p[r], o);
                    }
                    if (lane == 0) {
#pragma unroll
                        for (int r = 0; r < 4; r++)
                            g_score[b * SS + sbase + r] = p[r];
                    }
                    publish(&g_sdone[b]);
                } else {
                    const int jj  = j - F_CTX;
                    const int b   = jj >> 3;
                    const int sc0 = (jj & 7) * 128;
                    wait_ctr(&g_sdone[b], 64u);
                    const int w = tid >> 5, lane = tid & 31;
                    float* red = sh;
                    float* wal = sh + 16;
                    float s8[8];
                    {
                        float4 a  = *(const float4*)(g_score + b * SS + tid * 8);
                        float4 b4 = *(const float4*)(g_score + b * SS + tid * 8 + 4);
                        s8[0]=a.x; s8[1]=a.y; s8[2]=a.z; s8[3]=a.w;
                        s8[4]=b4.x; s8[5]=b4.y; s8[6]=b4.z; s8[7]=b4.w;
                    }
                    float mx = s8[0];
#pragma unroll
                    for (int i = 1; i < 8; i++) mx = fmaxf(mx, s8[i]);
#pragma unroll
                    for (int o = 16; o; o >>= 1) mx = fmaxf(mx, __shfl_xor_sync(0xFFFFFFFFu, mx, o));
                    __syncthreads();
                    if (lane == 0) red[w] = mx;
                    __syncthreads();
                    mx = fmaxf(fmaxf(red[0], red[1]), fmaxf(red[2], red[3]));
                    float e8[8], lsum = 0.f;
#pragma unroll
                    for (int i = 0; i < 8; i++) { e8[i] = __expf(s8[i] - mx); lsum += e8[i]; }
#pragma unroll
                    for (int o = 16; o; o >>= 1) lsum += __shfl_xor_sync(0xFFFFFFFFu, lsum, o);
                    __syncthreads();
                    if (lane == 0) red[4 + w] = lsum;
                    __syncthreads();
                    float inv = 1.0f / (red[4] + red[5] + red[6] + red[7]);
                    {
                        int p0 = tid * 8;
                        if (p0 >= sc0 && p0 < sc0 + 128) {
#pragma unroll
                            for (int i = 0; i < 8; i++) wal[p0 - sc0 + i] = e8[i] * inv;
                        }
                    }
                    __syncthreads();
                    const int u0 = tid * 8;
                    const __half* mp = g_memh + ((size_t)b * SS + sc0) * UU + u0;
                    float4 a0 = make_float4(0.f, 0.f, 0.f, 0.f);
                    float4 a1 = make_float4(0.f, 0.f, 0.f, 0.f);
#pragma unroll 4
                    for (int s = 0; s < 128; s++) {
                        float wv = wal[s];
                        uint4 raw = *(const uint4*)(mp + (size_t)s * UU);
                        float2 f0 = h2f2(raw.x);
                        float2 f1 = h2f2(raw.y);
                        float2 f2 = h2f2(raw.z);
                        float2 f3 = h2f2(raw.w);
                        a0.x += wv * f0.x; a0.y += wv * f0.y;
                        a0.z += wv * f1.x; a0.w += wv * f1.y;
                        a1.x += wv * f2.x; a1.y += wv * f2.y;
                        a1.z += wv * f3.x; a1.w += wv * f3.y;
                    }
                    float* cp = g_ctx + b * UU + u0;
                    atomicAdd(cp + 0, a0.x); atomicAdd(cp + 1, a0.y);
                    atomicAdd(cp + 2, a0.z); atomicAdd(cp + 3, a0.w);
                    atomicAdd(cp + 4, a1.x); atomicAdd(cp + 5, a1.y);
                    atomicAdd(cp + 6, a1.z); atomicAdd(cp + 7, a1.w);
                    __syncthreads();
                }
            }
        }
        grid_sync();

        // ---- P7 (HMMA): attn part2 (ctx cols)  (128 jobs, k=256) ----
        for (int j = bid; j < 128; j += NCTA) {
            const int n0 = (j & 31) * BN;
            const int kb = 1024 + (j >> 5) * 256;
            auto fA = [&](int m, int k) -> float4 {
                return *(const float4*)(g_ctx + m * UU + (k - 1024));
            };
            auto fB = [&](int k, int c8) -> uint4 {
                return *(const uint4*)(g_WaH + (size_t)k * UU + n0 + c8);
            };
            auto epi = [&](int r, int c, float val) {
                atomicAdd(&g_attn[r * UU + n0 + c], val);
            };
            hmma_tile(sh, fA, fB, epi, kb, kb + 256);
        }
        grid_sync();

        // ---- P8 (all HMMA): out(t) += attn @ WfcH [256 k128] + lstm2(t+1) [512 k256] ----
        {
            const int nj = more_t ? 768 : 256;
            for (int j = bid; j < nj; j += NCTA) {
                if (j < 256) {
                    const int n0 = (j & 31) * BN;
                    const int kb = (j >> 5) * 128;
                    auto fA = [&](int m, int k) -> float4 {
                        return *(const float4*)(g_attn + m * UU + k);
                    };
                    auto fB = [&](int k, int c8) -> uint4 {
                        return *(const uint4*)(g_WfcH + (size_t)k * VV + n0 + c8);
                    };
                    auto epi = [&](int r, int c, float val) {
                        atomicAdd(out + ((size_t)r * TT + t) * VV + n0 + c, val);
                    };
                    hmma_tile(sh, fA, fB, epi, kb, kb + 128);
                } else {
                    const int jj = j - 256;               // 0..511
                    const int tile = jj & 127;
                    const int kb = 512 + (jj >> 7) * 256; // attn cols [512,1536)
                    lstm_chunk(tile, kb, kb + 256, t + 1);
                }
            }
        }
        grid_sync();
    }
}

// ---------------- host launcher: ONE graph node ----------------
extern "C" void kernel_launch(void* const* d_in, const int* in_sizes, int n_in,
                              void* d_out, int out_size)
{
    const int*   tokens = (const int*)  d_in[0];
    const float* memory = (const float*)d_in[1];
    const float* enc_h  = (const float*)d_in[2];
    const float* enc_c  = (const float*)d_in[3];
    const float* emb    = (const float*)d_in[4];
    const float* Wk     = (const float*)d_in[5];
    const float* Wr     = (const float*)d_in[6];
    const float* bias   = (const float*)d_in[7];
    const float* Wm     = (const float*)d_in[8];
    const float* Wq     = (const float*)d_in[9];
    const float* v      = (const float*)d_in[10];
    const float* Wa     = (const float*)d_in[11];
    const float* Wfc    = (const float*)d_in[12];
    const float* bfc    = (const float*)d_in[13];
    float* out = (float*)d_out;

    decoder_mega<<<NCTA, NTH>>>(tokens, memory, enc_h, enc_c, emb, Wk, Wr, bias,
                                Wm, Wq, v, Wa, Wfc, bfc, out);
}